// round 13
// baseline (speedup 1.0000x reference)
#include <cuda_runtime.h>
#include <cuda_fp16.h>
#include <math.h>
#include <stdint.h>

// ---------------------------------------------------------------------------
// Problem constants
// ---------------------------------------------------------------------------
#define BSZ  8192
#define DD   1024
#define NTOT 16384
#define TEMPI 20.0f
#define EPSN 1e-8f
#define LSE_SHIFT 20.0f       // sims = 20*cos <= 20 strictly

// GEMM tiling (fp16 m16n8k16, fp16 segment accum), 256 thr = 8 warps (2x4),
// warp tile 64x64
#define TM 128
#define TN 256
#define TK 64                  // K halves per chunk = 128 B per row
#define NSTAGE 3
#define CHUNKS (DD / TK)       // 16
#define NTILES (NTOT / TN)     // 64

#define A_BYTES (TM * 128)                 // 16384
#define B_BYTES (TN * 128)                 // 32768
#define STAGE_BYTES (A_BYTES + B_BYTES)    // 49152
#define SMEM_TOTAL (NSTAGE * STAGE_BYTES)  // 147456

// ---------------------------------------------------------------------------
// Scratch: fp16, PAIR-INTERLEAVED within each 8-pair (16-elem) group:
// pair j (= k>>1) sits at slot 2*(j&3) + ((j&7)>>2) of its group.
// ---------------------------------------------------------------------------
__device__ __half g_pn[BSZ * DD];
__device__ __half g_en[BSZ * DD];
__device__ __half g_cn[BSZ * DD];
__device__ float  g_psum[BSZ * NTILES];
__device__ float  g_rowloss[BSZ];

// ---------------------------------------------------------------------------
// helpers
// ---------------------------------------------------------------------------
__device__ __forceinline__ uint32_t smem_u32(const void* p) {
    uint32_t a;
    asm("{ .reg .u64 t; cvta.to.shared.u64 t, %1; cvt.u32.u64 %0, t; }" : "=r"(a) : "l"(p));
    return a;
}
__device__ __forceinline__ void cp_async16(uint32_t dst, const void* src) {
    asm volatile("cp.async.cg.shared.global [%0], [%1], 16;" :: "r"(dst), "l"(src) : "memory");
}
__device__ __forceinline__ void cp_commit() {
    asm volatile("cp.async.commit_group;" ::: "memory");
}
__device__ __forceinline__ void cp_wait_1() {
    asm volatile("cp.async.wait_group 1;" ::: "memory");
}
// fp16-accumulator MMA: D (2 regs, 4 halves) = A*B + C
__device__ __forceinline__ void mma_f16acc(uint32_t* d,
                                           uint32_t a0, uint32_t a1, uint32_t a2, uint32_t a3,
                                           uint32_t b0, uint32_t b1,
                                           uint32_t c0, uint32_t c1) {
    asm volatile(
        "mma.sync.aligned.m16n8k16.row.col.f16.f16.f16.f16 "
        "{%0,%1}, {%2,%3,%4,%5}, {%6,%7}, {%8,%9};"
        : "=r"(d[0]), "=r"(d[1])
        : "r"(a0), "r"(a1), "r"(a2), "r"(a3), "r"(b0), "r"(b1), "r"(c0), "r"(c1));
}

// ---------------------------------------------------------------------------
// Kernel 1: L2-normalize rows, convert to fp16, store pair-interleaved.
// grid=(BSZ,3), block=256
// ---------------------------------------------------------------------------
__global__ void normalize_kernel(const float* __restrict__ p,
                                 const float* __restrict__ e,
                                 const float* __restrict__ c) {
    int row   = blockIdx.x;
    int which = blockIdx.y;
    const float* src = (which == 0) ? p : (which == 1) ? e : c;
    __half*      dst = (which == 0) ? g_pn : (which == 1) ? g_en : g_cn;

    float4 v = reinterpret_cast<const float4*>(src + (size_t)row * DD)[threadIdx.x];
    float ss = v.x * v.x + v.y * v.y + v.z * v.z + v.w * v.w;
    #pragma unroll
    for (int off = 16; off; off >>= 1) ss += __shfl_xor_sync(0xffffffffu, ss, off);

    __shared__ float red[8];
    __shared__ float s_inv;
    if ((threadIdx.x & 31) == 0) red[threadIdx.x >> 5] = ss;
    __syncthreads();
    if (threadIdx.x == 0) {
        float tot = 0.f;
        #pragma unroll
        for (int i = 0; i < 8; i++) tot += red[i];
        s_inv = 1.0f / fmaxf(sqrtf(tot), EPSN);
    }
    __syncthreads();
    float inv = s_inv;

    __half2* drow = reinterpret_cast<__half2*>(dst + (size_t)row * DD);
    int t = threadIdx.x;
    #pragma unroll
    for (int q = 0; q < 2; q++) {
        int j  = 2 * t + q;
        int g  = j >> 3, jj = j & 7;
        int slot = 2 * (jj & 3) + (jj >> 2);
        float lo = q ? v.z : v.x;
        float hi = q ? v.w : v.y;
        drow[g * 8 + slot] = __floats2half2_rn(lo * inv, hi * inv);
    }
}

// ---------------------------------------------------------------------------
// Kernel 2: pipelined fp16 GEMM with fp16 per-chunk segment accumulators,
// promoted to fp32 once per chunk. 128x256 tile, 8 warps (2x4), warp 64x64,
// nt processed in two halves of 4 (reusing fp16 acc regs).
// ---------------------------------------------------------------------------
__global__ void __launch_bounds__(256, 1) gemm_kernel(float* __restrict__ out) {
    extern __shared__ char smem[];
    char* Sc = smem;
    uint32_t sb = smem_u32(smem);

    int tid = threadIdx.x;
    int wid = tid >> 5, lane = tid & 31;
    int grp = lane >> 2, tig = lane & 3;
    int wm = wid >> 2;          // 0..1  (M)
    int wn = wid & 3;           // 0..3  (N)

    int bx = blockIdx.x, by = blockIdx.y;
    int ctaM = by * TM, ctaN = bx * TN;

    const __half* Abase = g_pn + (size_t)ctaM * DD;
    const __half* Bbase = (ctaN < BSZ) ? (g_en + (size_t)ctaN * DD)
                                       : (g_cn + (size_t)(ctaN - BSZ) * DD);

    float acc[4][8][4];
    #pragma unroll
    for (int mt = 0; mt < 4; mt++)
        #pragma unroll
        for (int nt = 0; nt < 8; nt++)
            #pragma unroll
            for (int k = 0; k < 4; k++) acc[mt][nt][k] = 0.f;

    // cp.async coordinates: 256 threads, 16B granules, 8 per 128B row
    int lrow = tid >> 3;                 // 0..31
    int c16  = tid & 7;
    auto dsw = [&](int r) -> uint32_t {
        return (uint32_t)((r * 128 + c16 * 16) ^ ((r & 3) << 5));
    };

    auto load_chunk = [&](int nc, int s) {
        uint32_t stage = sb + s * STAGE_BYTES;
        const __half* Ab = Abase + nc * TK;
        const __half* Bb = Bbase + nc * TK;
        #pragma unroll
        for (int j = 0; j < 4; j++) {
            int r = lrow + 32 * j;
            cp_async16(stage + dsw(r), Ab + (size_t)r * DD + c16 * 8);
        }
        #pragma unroll
        for (int j = 0; j < 8; j++) {
            int r = lrow + 32 * j;
            cp_async16(stage + A_BYTES + dsw(r), Bb + (size_t)r * DD + c16 * 8);
        }
    };

    // ---- prologue ----
    load_chunk(0, 0); cp_commit();
    load_chunk(1, 1); cp_commit();

    uint32_t axor = (uint32_t)((grp & 3) << 5);
    int a_row0 = wm * 64 + grp;

    // ---- mainloop ----
    #pragma unroll 1
    for (int i = 0; i < CHUNKS; i++) {
        cp_wait_1();
        __syncthreads();
        int s = i % NSTAGE;
        const char* As = Sc + s * STAGE_BYTES;
        const char* Bs = As + A_BYTES;

        if (i + 2 < CHUNKS) load_chunk(i + 2, (i + 2) % NSTAGE);
        cp_commit();

        // two nt-halves, fp16 segment accumulators reused across halves
        #pragma unroll
        for (int h = 0; h < 2; h++) {
            uint32_t cc[4][4][2];   // [mt][nt'][2 regs of fp16x2]
            int b_row0 = wn * 64 + h * 32 + grp;

            #pragma unroll
            for (int kb = 0; kb < 4; kb++) {
                uint32_t wo = ((uint32_t)(kb * 32)) ^ axor;
                uint2 fa[4][2];
                uint2 fb[4];
                #pragma unroll
                for (int mt = 0; mt < 4; mt++) {
                    int r = a_row0 + mt * 16;
                    fa[mt][0] = *(const uint2*)(As + r * 128 + wo + tig * 8);
                    fa[mt][1] = *(const uint2*)(As + (r + 8) * 128 + wo + tig * 8);
                }
                #pragma unroll
                for (int nt = 0; nt < 4; nt++) {
                    int r = b_row0 + nt * 8;
                    fb[nt] = *(const uint2*)(Bs + r * 128 + wo + tig * 8);
                }
                #pragma unroll
                for (int mt = 0; mt < 4; mt++)
                    #pragma unroll
                    for (int nt = 0; nt < 4; nt++) {
                        uint32_t c0 = (kb == 0) ? 0u : cc[mt][nt][0];
                        uint32_t c1 = (kb == 0) ? 0u : cc[mt][nt][1];
                        mma_f16acc(cc[mt][nt],
                                   fa[mt][0].x, fa[mt][1].x,
                                   fa[mt][0].y, fa[mt][1].y,
                                   fb[nt].x, fb[nt].y, c0, c1);
                    }
            }
            // promote fp16 segment sums into fp32 accumulators
            #pragma unroll
            for (int mt = 0; mt < 4; mt++)
                #pragma unroll
                for (int nt = 0; nt < 4; nt++) {
                    float2 f01 = __half22float2(*reinterpret_cast<__half2*>(&cc[mt][nt][0]));
                    float2 f23 = __half22float2(*reinterpret_cast<__half2*>(&cc[mt][nt][1]));
                    float* a4 = acc[mt][h * 4 + nt];
                    a4[0] += f01.x; a4[1] += f01.y;
                    a4[2] += f23.x; a4[3] += f23.y;
                }
        }
    }
    __syncthreads();   // stages dead; smem reused below

    // ---- epilogue: scale, store sims, fused partial LSE ----
    float* simout = out + 1;
    float* sred = reinterpret_cast<float*>(smem);   // 128 rows x 4 wn partials

    #pragma unroll
    for (int mt = 0; mt < 4; mt++) {
        int rl0 = wm * 64 + mt * 16 + grp;     // local row (0..127)
        int r0 = ctaM + rl0;
        size_t rb0 = (size_t)r0 * NTOT + ctaN + wn * 64;
        size_t rb1 = rb0 + (size_t)8 * NTOT;
        float s0 = 0.f, s1 = 0.f;
        #pragma unroll
        for (int nt = 0; nt < 8; nt++) {
            int cof = nt * 8 + tig * 2;
            float v0 = acc[mt][nt][0] * TEMPI;
            float v1 = acc[mt][nt][1] * TEMPI;
            float v2 = acc[mt][nt][2] * TEMPI;
            float v3 = acc[mt][nt][3] * TEMPI;
            simout[rb0 + cof]     = v0;
            simout[rb0 + cof + 1] = v1;
            simout[rb1 + cof]     = v2;
            simout[rb1 + cof + 1] = v3;
            s0 += __expf(v0 - LSE_SHIFT) + __expf(v1 - LSE_SHIFT);
            s1 += __expf(v2 - LSE_SHIFT) + __expf(v3 - LSE_SHIFT);
        }
        s0 += __shfl_xor_sync(0xffffffffu, s0, 1);
        s0 += __shfl_xor_sync(0xffffffffu, s0, 2);
        s1 += __shfl_xor_sync(0xffffffffu, s1, 1);
        s1 += __shfl_xor_sync(0xffffffffu, s1, 2);
        if (tig == 0) {
            sred[rl0 * 4 + wn]       = s0;
            sred[(rl0 + 8) * 4 + wn] = s1;
        }
    }
    __syncthreads();
    if (tid < TM) {
        float s = sred[tid * 4] + sred[tid * 4 + 1] + sred[tid * 4 + 2] + sred[tid * 4 + 3];
        g_psum[(size_t)(ctaM + tid) * NTILES + bx] = s;
    }
}

// ---------------------------------------------------------------------------
// Kernel 3: combine NTILES partial sums per row.  grid=BSZ, block=64
// ---------------------------------------------------------------------------
__global__ void lse_final_kernel(const float* __restrict__ sims) {
    int row = blockIdx.x;
    float s = g_psum[(size_t)row * NTILES + threadIdx.x];
    #pragma unroll
    for (int off = 16; off; off >>= 1) s += __shfl_xor_sync(0xffffffffu, s, off);
    __shared__ float red[2];
    if ((threadIdx.x & 31) == 0) red[threadIdx.x >> 5] = s;
    __syncthreads();
    if (threadIdx.x == 0) {
        float S = red[0] + red[1];
        float tgt = sims[(size_t)row * NTOT + row];
        g_rowloss[row] = LSE_SHIFT + logf(S) - tgt;
    }
}

// ---------------------------------------------------------------------------
// Kernel 4: mean over rows -> out[0]
// ---------------------------------------------------------------------------
__global__ void loss_kernel(float* __restrict__ out) {
    float s = 0.f;
    for (int i = threadIdx.x; i < BSZ; i += 256) s += g_rowloss[i];
    #pragma unroll
    for (int off = 16; off; off >>= 1) s += __shfl_xor_sync(0xffffffffu, s, off);
    __shared__ float red[8];
    if ((threadIdx.x & 31) == 0) red[threadIdx.x >> 5] = s;
    __syncthreads();
    if (threadIdx.x == 0) {
        float tot = 0.f;
        #pragma unroll
        for (int i = 0; i < 8; i++) tot += red[i];
        out[0] = tot / (float)BSZ;
    }
}

// ---------------------------------------------------------------------------
extern "C" void kernel_launch(void* const* d_in, const int* in_sizes, int n_in,
                              void* d_out, int out_size) {
    const float* p = (const float*)d_in[0];
    const float* e = (const float*)d_in[1];
    const float* c = (const float*)d_in[2];
    float* out = (float*)d_out;

    cudaFuncSetAttribute(gemm_kernel, cudaFuncAttributeMaxDynamicSharedMemorySize, SMEM_TOTAL);

    normalize_kernel<<<dim3(BSZ, 3), 256>>>(p, e, c);
    gemm_kernel<<<dim3(NTOT / TN, BSZ / TM), 256, SMEM_TOTAL>>>(out);
    lse_final_kernel<<<BSZ, 64>>>(out + 1);
    loss_kernel<<<1, 256>>>(out);
}

// round 17
// speedup vs baseline: 1.3887x; 1.3887x over previous
#include <cuda_runtime.h>
#include <cuda_fp16.h>
#include <math.h>
#include <stdint.h>

// ---------------------------------------------------------------------------
// Problem constants
// ---------------------------------------------------------------------------
#define BSZ  8192
#define DD   1024
#define NTOT 16384
#define TEMPI 20.0f
#define EPSN 1e-8f
#define LSE_SHIFT 20.0f       // sims = 20*cos <= 20 strictly

// GEMM tiling (fp16 m16n8k16), 256 thr = 8 warps (2 M x 4 N), warp 64x32,
// CTA tile 128x128, 2 CTAs/SM for prologue/epilogue overlap.
#define TM 128
#define TN 128
#define TK 64                  // K halves per chunk = 128 B per row
#define NSTAGE 3
#define CHUNKS (DD / TK)       // 16
#define NTILES (NTOT / TN)     // 128

#define A_BYTES (TM * 128)                 // 16384
#define B_BYTES (TN * 128)                 // 16384
#define STAGE_BYTES (A_BYTES + B_BYTES)    // 32768
#define SMEM_TOTAL (NSTAGE * STAGE_BYTES)  // 98304

// ---------------------------------------------------------------------------
// Scratch: fp16, PAIR-INTERLEAVED within each 8-pair (16-elem) group:
// pair j (= k>>1) sits at slot 2*(j&3) + ((j&7)>>2) of its group.
// ---------------------------------------------------------------------------
__device__ __half g_pn[BSZ * DD];
__device__ __half g_en[BSZ * DD];
__device__ __half g_cn[BSZ * DD];
__device__ float  g_psum[BSZ * NTILES];
__device__ float  g_rowloss[BSZ];

// ---------------------------------------------------------------------------
// helpers
// ---------------------------------------------------------------------------
__device__ __forceinline__ uint32_t smem_u32(const void* p) {
    uint32_t a;
    asm("{ .reg .u64 t; cvta.to.shared.u64 t, %1; cvt.u32.u64 %0, t; }" : "=r"(a) : "l"(p));
    return a;
}
__device__ __forceinline__ void cp_async16(uint32_t dst, const void* src) {
    asm volatile("cp.async.cg.shared.global [%0], [%1], 16;" :: "r"(dst), "l"(src) : "memory");
}
__device__ __forceinline__ void cp_commit() {
    asm volatile("cp.async.commit_group;" ::: "memory");
}
__device__ __forceinline__ void cp_wait_1() {
    asm volatile("cp.async.wait_group 1;" ::: "memory");
}
__device__ __forceinline__ void mma_f16(float* c,
                                        uint32_t a0, uint32_t a1, uint32_t a2, uint32_t a3,
                                        uint32_t b0, uint32_t b1) {
    asm volatile(
        "mma.sync.aligned.m16n8k16.row.col.f32.f16.f16.f32 "
        "{%0,%1,%2,%3}, {%4,%5,%6,%7}, {%8,%9}, {%0,%1,%2,%3};"
        : "+f"(c[0]), "+f"(c[1]), "+f"(c[2]), "+f"(c[3])
        : "r"(a0), "r"(a1), "r"(a2), "r"(a3), "r"(b0), "r"(b1));
}

// ---------------------------------------------------------------------------
// Kernel 1: L2-normalize rows, convert to fp16, store pair-interleaved.
// grid=(BSZ,3), block=256
// ---------------------------------------------------------------------------
__global__ void normalize_kernel(const float* __restrict__ p,
                                 const float* __restrict__ e,
                                 const float* __restrict__ c) {
    int row   = blockIdx.x;
    int which = blockIdx.y;
    const float* src = (which == 0) ? p : (which == 1) ? e : c;
    __half*      dst = (which == 0) ? g_pn : (which == 1) ? g_en : g_cn;

    float4 v = reinterpret_cast<const float4*>(src + (size_t)row * DD)[threadIdx.x];
    float ss = v.x * v.x + v.y * v.y + v.z * v.z + v.w * v.w;
    #pragma unroll
    for (int off = 16; off; off >>= 1) ss += __shfl_xor_sync(0xffffffffu, ss, off);

    __shared__ float red[8];
    __shared__ float s_inv;
    if ((threadIdx.x & 31) == 0) red[threadIdx.x >> 5] = ss;
    __syncthreads();
    if (threadIdx.x == 0) {
        float tot = 0.f;
        #pragma unroll
        for (int i = 0; i < 8; i++) tot += red[i];
        s_inv = 1.0f / fmaxf(sqrtf(tot), EPSN);
    }
    __syncthreads();
    float inv = s_inv;

    __half2* drow = reinterpret_cast<__half2*>(dst + (size_t)row * DD);
    int t = threadIdx.x;
    #pragma unroll
    for (int q = 0; q < 2; q++) {
        int j  = 2 * t + q;
        int g  = j >> 3, jj = j & 7;
        int slot = 2 * (jj & 3) + (jj >> 2);
        float lo = q ? v.z : v.x;
        float hi = q ? v.w : v.y;
        drow[g * 8 + slot] = __floats2half2_rn(lo * inv, hi * inv);
    }
}

// ---------------------------------------------------------------------------
// Kernel 2: pipelined fp16 m16n8k16 GEMM, 128x128 tile, 8 warps (2x4),
// warp tile 64x32, 3-stage cp.async ring, XOR swizzle, 2 CTAs/SM.
// Fused scale + partial-LSE epilogue.
// ---------------------------------------------------------------------------
__global__ void __launch_bounds__(256, 2) gemm_kernel(float* __restrict__ out) {
    extern __shared__ char smem[];
    char* Sc = smem;
    uint32_t sb = smem_u32(smem);

    int tid = threadIdx.x;
    int wid = tid >> 5, lane = tid & 31;
    int grp = lane >> 2, tig = lane & 3;
    int wm = wid >> 2;          // 0..1  (M)
    int wn = wid & 3;           // 0..3  (N)

    int bx = blockIdx.x, by = blockIdx.y;
    int ctaM = by * TM, ctaN = bx * TN;

    const __half* Abase = g_pn + (size_t)ctaM * DD;
    const __half* Bbase = (ctaN < BSZ) ? (g_en + (size_t)ctaN * DD)
                                       : (g_cn + (size_t)(ctaN - BSZ) * DD);

    float acc[4][4][4];
    #pragma unroll
    for (int mt = 0; mt < 4; mt++)
        #pragma unroll
        for (int nt = 0; nt < 4; nt++)
            #pragma unroll
            for (int k = 0; k < 4; k++) acc[mt][nt][k] = 0.f;

    // cp.async coordinates: 256 threads, 16B granules, 8 per 128B row
    int lrow = tid >> 3;                 // 0..31
    int c16  = tid & 7;
    auto dsw = [&](int r) -> uint32_t {
        return (uint32_t)((r * 128 + c16 * 16) ^ ((r & 3) << 5));
    };

    auto load_chunk = [&](int nc, int s) {
        uint32_t stage = sb + s * STAGE_BYTES;
        const __half* Ab = Abase + nc * TK;
        const __half* Bb = Bbase + nc * TK;
        #pragma unroll
        for (int j = 0; j < 4; j++) {
            int r = lrow + 32 * j;
            cp_async16(stage + dsw(r), Ab + (size_t)r * DD + c16 * 8);
        }
        #pragma unroll
        for (int j = 0; j < 4; j++) {
            int r = lrow + 32 * j;
            cp_async16(stage + A_BYTES + dsw(r), Bb + (size_t)r * DD + c16 * 8);
        }
    };

    // ---- prologue ----
    load_chunk(0, 0); cp_commit();
    load_chunk(1, 1); cp_commit();

    uint32_t axor = (uint32_t)((grp & 3) << 5);
    int a_row0 = wm * 64 + grp;
    int b_row0 = wn * 32 + grp;

    // ---- mainloop ----
    #pragma unroll 1
    for (int i = 0; i < CHUNKS; i++) {
        cp_wait_1();
        __syncthreads();
        int s = i % NSTAGE;
        const char* As = Sc + s * STAGE_BYTES;
        const char* Bs = As + A_BYTES;

        if (i + 2 < CHUNKS) load_chunk(i + 2, (i + 2) % NSTAGE);
        cp_commit();

        #pragma unroll
        for (int kb = 0; kb < 4; kb++) {
            uint32_t wo = ((uint32_t)(kb * 32)) ^ axor;
            uint2 fa[4][2];
            uint2 fb[4];
            #pragma unroll
            for (int mt = 0; mt < 4; mt++) {
                int r = a_row0 + mt * 16;
                fa[mt][0] = *(const uint2*)(As + r * 128 + wo + tig * 8);
                fa[mt][1] = *(const uint2*)(As + (r + 8) * 128 + wo + tig * 8);
            }
            #pragma unroll
            for (int nt = 0; nt < 4; nt++) {
                int r = b_row0 + nt * 8;
                fb[nt] = *(const uint2*)(Bs + r * 128 + wo + tig * 8);
            }
            #pragma unroll
            for (int mt = 0; mt < 4; mt++)
                #pragma unroll
                for (int nt = 0; nt < 4; nt++)
                    mma_f16(acc[mt][nt],
                            fa[mt][0].x, fa[mt][1].x,
                            fa[mt][0].y, fa[mt][1].y,
                            fb[nt].x, fb[nt].y);
        }
    }
    __syncthreads();   // stages dead; smem reused below

    // ---- epilogue: scale, store sims, fused partial LSE ----
    float* simout = out + 1;
    float* sred = reinterpret_cast<float*>(smem);   // 128 rows x 4 wn partials

    #pragma unroll
    for (int mt = 0; mt < 4; mt++) {
        int rl0 = wm * 64 + mt * 16 + grp;     // local row (0..127)
        int r0 = ctaM + rl0;
        size_t rb0 = (size_t)r0 * NTOT + ctaN + wn * 32;
        size_t rb1 = rb0 + (size_t)8 * NTOT;
        float s0 = 0.f, s1 = 0.f;
        #pragma unroll
        for (int nt = 0; nt < 4; nt++) {
            int cof = nt * 8 + tig * 2;
            float v0 = acc[mt][nt][0] * TEMPI;
            float v1 = acc[mt][nt][1] * TEMPI;
            float v2 = acc[mt][nt][2] * TEMPI;
            float v3 = acc[mt][nt][3] * TEMPI;
            simout[rb0 + cof]     = v0;
            simout[rb0 + cof + 1] = v1;
            simout[rb1 + cof]     = v2;
            simout[rb1 + cof + 1] = v3;
            s0 += __expf(v0 - LSE_SHIFT) + __expf(v1 - LSE_SHIFT);
            s1 += __expf(v2 - LSE_SHIFT) + __expf(v3 - LSE_SHIFT);
        }
        s0 += __shfl_xor_sync(0xffffffffu, s0, 1);
        s0 += __shfl_xor_sync(0xffffffffu, s0, 2);
        s1 += __shfl_xor_sync(0xffffffffu, s1, 1);
        s1 += __shfl_xor_sync(0xffffffffu, s1, 2);
        if (tig == 0) {
            sred[rl0 * 4 + wn]       = s0;
            sred[(rl0 + 8) * 4 + wn] = s1;
        }
    }
    __syncthreads();
    if (tid < TM) {
        float s = sred[tid * 4] + sred[tid * 4 + 1] + sred[tid * 4 + 2] + sred[tid * 4 + 3];
        g_psum[(size_t)(ctaM + tid) * NTILES + bx] = s;
    }
}

// ---------------------------------------------------------------------------
// Kernel 3: combine NTILES partial sums per row.  grid=BSZ, block=128
// ---------------------------------------------------------------------------
__global__ void lse_final_kernel(const float* __restrict__ sims) {
    int row = blockIdx.x;
    float s = g_psum[(size_t)row * NTILES + threadIdx.x];
    #pragma unroll
    for (int off = 16; off; off >>= 1) s += __shfl_xor_sync(0xffffffffu, s, off);
    __shared__ float red[4];
    if ((threadIdx.x & 31) == 0) red[threadIdx.x >> 5] = s;
    __syncthreads();
    if (threadIdx.x == 0) {
        float S = red[0] + red[1] + red[2] + red[3];
        float tgt = sims[(size_t)row * NTOT + row];
        g_rowloss[row] = LSE_SHIFT + logf(S) - tgt;
    }
}

// ---------------------------------------------------------------------------
// Kernel 4: mean over rows -> out[0]
// ---------------------------------------------------------------------------
__global__ void loss_kernel(float* __restrict__ out) {
    float s = 0.f;
    for (int i = threadIdx.x; i < BSZ; i += 256) s += g_rowloss[i];
    #pragma unroll
    for (int off = 16; off; off >>= 1) s += __shfl_xor_sync(0xffffffffu, s, off);
    __shared__ float red[8];
    if ((threadIdx.x & 31) == 0) red[threadIdx.x >> 5] = s;
    __syncthreads();
    if (threadIdx.x == 0) {
        float tot = 0.f;
        #pragma unroll
        for (int i = 0; i < 8; i++) tot += red[i];
        out[0] = tot / (float)BSZ;
    }
}

// ---------------------------------------------------------------------------
extern "C" void kernel_launch(void* const* d_in, const int* in_sizes, int n_in,
                              void* d_out, int out_size) {
    const float* p = (const float*)d_in[0];
    const float* e = (const float*)d_in[1];
    const float* c = (const float*)d_in[2];
    float* out = (float*)d_out;

    cudaFuncSetAttribute(gemm_kernel, cudaFuncAttributeMaxDynamicSharedMemorySize, SMEM_TOTAL);

    normalize_kernel<<<dim3(BSZ, 3), 256>>>(p, e, c);
    gemm_kernel<<<dim3(NTOT / TN, BSZ / TM), 256, SMEM_TOTAL>>>(out);
    lse_final_kernel<<<BSZ, 128>>>(out + 1);
    loss_kernel<<<1, 256>>>(out);
}